// round 14
// baseline (speedup 1.0000x reference)
#include <cuda_runtime.h>
#include <cuda_fp16.h>
#include <cstdint>

#define CC       64
#define OUTC     256
#define HWN      4096
#define NCHUNK   65
#define PTILE    128
#define NTHREADS 512
#define WSTRIDE  (OUTC*CC)          // 16384 halves per weight chunk

// smem byte offsets
#define SM_XS    0                   // 64 x 128 fp32 = 32KB
#define SM_A     32768               // 2 stages x 32KB  ([256 o][64 k] f16, 128B rows)
#define SM_B     (32768 + 65536)     // 2 stages x 16KB  ([128 p][64 k] f16, 128B rows)
#define SM_TOTAL (SM_B + 32768)      // 128KB

#define SWZ(o) ((o) ^ (((o) >> 3) & 0x70))

__device__ __align__(16) __half g_Wh[NCHUNK * WSTRIDE];   // 2.1MB prepared f16 weights

__device__ __forceinline__ uint32_t s2u(const void* p) {
    uint32_t a;
    asm("{ .reg .u64 t; cvta.to.shared.u64 t, %1; cvt.u32.u64 %0, t; }" : "=r"(a) : "l"(p));
    return a;
}
__device__ __forceinline__ void cp16(uint32_t dst, const void* src) {
    asm volatile("cp.async.cg.shared.global [%0], [%1], 16;" :: "r"(dst), "l"(src) : "memory");
}
#define CP_COMMIT() asm volatile("cp.async.commit_group;" ::: "memory")
#define CP_WAIT0()  asm volatile("cp.async.wait_group 0;" ::: "memory")

__device__ __forceinline__ void ldsm_x4(uint32_t a, uint32_t& r0, uint32_t& r1, uint32_t& r2, uint32_t& r3) {
    asm volatile("ldmatrix.sync.aligned.m8n8.x4.shared.b16 {%0,%1,%2,%3}, [%4];"
                 : "=r"(r0), "=r"(r1), "=r"(r2), "=r"(r3) : "r"(a));
}
__device__ __forceinline__ void mma16816(float* d, const uint32_t* a, const uint32_t* b) {
    asm volatile("mma.sync.aligned.m16n8k16.row.col.f32.f16.f16.f32 "
                 "{%0,%1,%2,%3}, {%4,%5,%6,%7}, {%8,%9}, {%0,%1,%2,%3};"
                 : "+f"(d[0]), "+f"(d[1]), "+f"(d[2]), "+f"(d[3])
                 : "r"(a[0]), "r"(a[1]), "r"(a[2]), "r"(a[3]), "r"(b[0]), "r"(b[1]));
}

// ---- weight prep: fc_w fp32 [256 x 2144] -> g_Wh f16 [chunk][o][k], zero below diag ----
__global__ void prep_kernel(const float* __restrict__ fc_w) {
    int idx = blockIdx.x * blockDim.x + threadIdx.x;   // exactly 65*16384
    int chunk = idx >> 14;
    int rem = idx & 16383;
    int o = rem >> 6;
    int k = rem & 63;
    float v = 0.0f;
    if (chunk == 64) {
        v = fc_w[o * 2144 + k];                                // linear part
    } else if (k >= chunk) {
        int off = 64 + chunk * 64 - (chunk * (chunk - 1)) / 2 + (k - chunk);
        v = fc_w[o * 2144 + off];                              // triu(i=chunk, j=k)
    }
    g_Wh[idx] = __float2half_rn(v);
}

__device__ __forceinline__ void load_A(uint32_t dstStage, int chunk, int tid) {
    const int ks16 = (chunk < 64) ? (chunk >> 4) : 0;
    const int o = tid >> 1, h = tid & 1;
    const __half* src = g_Wh + (size_t)chunk * WSTRIDE + o * 64 + h * 8;
#pragma unroll
    for (int kt = 0; kt < 4; kt++) {
        if (kt >= ks16) {
            uint32_t d = dstStage + SWZ((uint32_t)(o * 128 + kt * 32 + h * 16));
            cp16(d, src + kt * 16);
        }
    }
}

// produce B[chunk] into its stage buffer: B[p][k] = x_chunk[p]*x_k[p] in f16
__device__ __forceinline__ void produce_B(char* smem, const float* xs, int chunk, int bp, int bks) {
    const int ks16 = (chunk < 64) ? (chunk >> 4) : 0;
    if (bks < ks16) return;
    const float xi = (chunk < 64) ? xs[chunk * PTILE + bp] : 1.0f;
    __half2 h[8];
#pragma unroll
    for (int j = 0; j < 8; j++) {
        float a0 = xs[(bks * 16 + 2 * j) * PTILE + bp];
        float a1 = xs[(bks * 16 + 2 * j + 1) * PTILE + bp];
        h[j] = __floats2half2_rn(xi * a0, xi * a1);
    }
    char* bbase = smem + SM_B + (chunk & 1) * 16384;
    const uint32_t ro = (uint32_t)bp * 128 + bks * 32;
    *(uint4*)(bbase + SWZ(ro))      = *(uint4*)&h[0];
    *(uint4*)(bbase + SWZ(ro + 16)) = *(uint4*)&h[4];
}

// ---- main: 256 CTAs x 512 threads; CTA = 256 outputs x 128 pixels ----
__global__ void __launch_bounds__(NTHREADS, 1)
quad_main(const float* __restrict__ x, float* __restrict__ out) {
    extern __shared__ __align__(1024) char smem[];
    const uint32_t sb = s2u(smem);
    const int tid = threadIdx.x;
    const int lane = tid & 31;
    const int wid = tid >> 5;
    const int mw = wid & 3;          // output  64-block
    const int nw = wid >> 2;         // pixel   32-block

    const int bidx = blockIdx.x >> 5;          // batch
    const int hw0  = (blockIdx.x & 31) << 7;   // pixel tile base (128)

    float* xs = (float*)(smem + SM_XS);        // [c][p] fp32

    // prefetch A chunk 0
    load_A(sb + SM_A, 0, tid);
    CP_COMMIT();

    // load x tile [64][128]
    {
        const float4* xg = (const float4*)(x + (size_t)bidx * CC * HWN + hw0);
#pragma unroll
        for (int j = 0; j < 4; j++) {
            int idx = tid + j * NTHREADS;       // 0..2047
            int c = idx >> 5, p4 = idx & 31;
            ((float4*)xs)[c * 32 + p4] = xg[(size_t)c * (HWN / 4) + p4];
        }
    }
    CP_WAIT0();          // own A0 copies done before barrier
    __syncthreads();     // publishes x tile AND everyone's A0 copies

    // producer mapping: lane-contiguous pixels -> conflict-free LDS
    const int bp  = tid & 127;      // producer pixel
    const int bks = tid >> 7;       // producer k-block (uniform per warp)

    // produce B[0], publish
    produce_B(smem, xs, 0, bp, bks);
    __syncthreads();

    // lane-derived ldmatrix offsets
    const int arow  = (lane & 7) + ((lane >> 3) & 1) * 8;   // A: row within 16
    const int acol  = ((lane >> 4) & 1) * 16;               // A: byte offset (hi 8 halves)
    const int b4row = (lane & 7) + ((lane >> 4) & 1) * 8;   // B x4: row within 16 (n)
    const int b4col = ((lane >> 3) & 1) * 16;               // B x4: byte offset (k half)

    float acc[4][4][4];
#pragma unroll
    for (int a = 0; a < 4; a++)
#pragma unroll
        for (int b = 0; b < 4; b++)
#pragma unroll
            for (int c = 0; c < 4; c++) acc[a][b][c] = 0.0f;

#pragma unroll 1
    for (int chunk = 0; chunk < NCHUNK; chunk++) {
        const int s = chunk & 1;
        const int ks16 = (chunk < 64) ? (chunk >> 4) : 0;

        // 1) produce NEXT chunk's B into the other buffer (its readers finished
        //    before the previous barrier) — overlaps with mma across warps
        if (chunk + 1 < NCHUNK)
            produce_B(smem, xs, chunk + 1, bp, bks);

        // 2) prefetch NEXT A into the buffer freed at the previous barrier
        if (chunk + 1 < NCHUNK) {
            load_A(sb + SM_A + (s ^ 1) * 32768, chunk + 1, tid);
            CP_COMMIT();
        }

        // 3) mma on A[s], B[s] — both published by the previous barrier
        const uint32_t aA = sb + SM_A + s * 32768;
        const uint32_t aB = sb + SM_B + s * 16384;

#pragma unroll
        for (int kt = 0; kt < 4; kt++) {
            if (kt >= ks16) {
                uint32_t af[4][4];
#pragma unroll
                for (int mt = 0; mt < 4; mt++) {
                    uint32_t addr = aA + SWZ((uint32_t)((mw * 64 + mt * 16 + arow) * 128 + kt * 32 + acol));
                    ldsm_x4(addr, af[mt][0], af[mt][1], af[mt][2], af[mt][3]);
                }
                uint32_t bf[4][2];
#pragma unroll
                for (int nt2 = 0; nt2 < 2; nt2++) {
                    uint32_t addr = aB + SWZ((uint32_t)((nw * 32 + nt2 * 16 + b4row) * 128 + kt * 32 + b4col));
                    ldsm_x4(addr, bf[nt2 * 2][0], bf[nt2 * 2][1], bf[nt2 * 2 + 1][0], bf[nt2 * 2 + 1][1]);
                }
#pragma unroll
                for (int mt = 0; mt < 4; mt++)
#pragma unroll
                    for (int nt = 0; nt < 4; nt++)
                        mma16816(acc[mt][nt], af[mt], bf[nt]);
            }
        }

        // 4) own A[chunk+1] copies complete BEFORE the barrier (cross-thread
        //    cp.async visibility requires wait-then-barrier, not wait alone)
        CP_WAIT0();

        // 5) single barrier: publishes B[chunk+1] stores + all A[chunk+1] copies,
        //    and frees A[s]/B[s] for the next iteration's writes
        __syncthreads();
    }

    // ---- epilogue: fp32 accumulators -> out[b][o][hw] ----
#pragma unroll
    for (int mt = 0; mt < 4; mt++) {
#pragma unroll
        for (int nt = 0; nt < 4; nt++) {
            const int o = mw * 64 + mt * 16 + (lane >> 2);
            const int p = nw * 32 + nt * 8 + (lane & 3) * 2;
            float* op = out + ((size_t)bidx * OUTC + o) * HWN + hw0 + p;
            float2 v0 = make_float2(acc[mt][nt][0], acc[mt][nt][1]);
            float2 v1 = make_float2(acc[mt][nt][2], acc[mt][nt][3]);
            *(float2*)op = v0;
            *(float2*)(op + 8 * HWN) = v1;
        }
    }
}

extern "C" void kernel_launch(void* const* d_in, const int* in_sizes, int n_in,
                              void* d_out, int out_size) {
    const float* x    = (const float*)d_in[0];
    const float* fc_w = (const float*)d_in[1];
    float* out = (float*)d_out;

    cudaFuncSetAttribute(quad_main, cudaFuncAttributeMaxDynamicSharedMemorySize, SM_TOTAL);

    prep_kernel<<<1040, 1024>>>(fc_w);            // 65*16384 threads exactly
    quad_main<<<256, NTHREADS, SM_TOTAL>>>(x, out);
}

// round 16
// speedup vs baseline: 1.0230x; 1.0230x over previous
#include <cuda_runtime.h>
#include <cuda_fp16.h>
#include <cstdint>

#define CC       64
#define OUTC     256
#define HWN      4096
#define NCHUNK   65
#define PTILE    128
#define NTHREADS 256
#define WSTRIDE  (OUTC*CC)          // 16384 halves per weight chunk

// smem byte offsets (per CTA: 96KB -> 2 CTAs/SM)
#define SM_XS    0                   // 64 x 128 fp32 = 32KB
#define SM_A     32768               // 2 stages x 16KB ([128 o][64 k] f16, 128B rows)
#define SM_B     65536               // 2 stages x 16KB ([128 p][64 k] f16, 128B rows)
#define SM_TOTAL 98304

#define SWZ(o) ((o) ^ (((o) >> 3) & 0x70))

__device__ __align__(16) __half g_Wh[NCHUNK * WSTRIDE];   // 2.1MB prepared f16 weights

__device__ __forceinline__ uint32_t s2u(const void* p) {
    uint32_t a;
    asm("{ .reg .u64 t; cvta.to.shared.u64 t, %1; cvt.u32.u64 %0, t; }" : "=r"(a) : "l"(p));
    return a;
}
__device__ __forceinline__ void cp16(uint32_t dst, const void* src) {
    asm volatile("cp.async.cg.shared.global [%0], [%1], 16;" :: "r"(dst), "l"(src) : "memory");
}
#define CP_COMMIT() asm volatile("cp.async.commit_group;" ::: "memory")
#define CP_WAIT0()  asm volatile("cp.async.wait_group 0;" ::: "memory")

__device__ __forceinline__ void ldsm_x4(uint32_t a, uint32_t& r0, uint32_t& r1, uint32_t& r2, uint32_t& r3) {
    asm volatile("ldmatrix.sync.aligned.m8n8.x4.shared.b16 {%0,%1,%2,%3}, [%4];"
                 : "=r"(r0), "=r"(r1), "=r"(r2), "=r"(r3) : "r"(a));
}
__device__ __forceinline__ void mma16816(float* d, const uint32_t* a, const uint32_t* b) {
    asm volatile("mma.sync.aligned.m16n8k16.row.col.f32.f16.f16.f32 "
                 "{%0,%1,%2,%3}, {%4,%5,%6,%7}, {%8,%9}, {%0,%1,%2,%3};"
                 : "+f"(d[0]), "+f"(d[1]), "+f"(d[2]), "+f"(d[3])
                 : "r"(a[0]), "r"(a[1]), "r"(a[2]), "r"(a[3]), "r"(b[0]), "r"(b[1]));
}

// ---- weight prep: fc_w fp32 [256 x 2144] -> g_Wh f16 [chunk][o][k], zero below diag ----
__global__ void prep_kernel(const float* __restrict__ fc_w) {
    int idx = blockIdx.x * blockDim.x + threadIdx.x;   // exactly 65*16384
    int chunk = idx >> 14;
    int rem = idx & 16383;
    int o = rem >> 6;
    int k = rem & 63;
    float v = 0.0f;
    if (chunk == 64) {
        v = fc_w[o * 2144 + k];                                // linear part
    } else if (k >= chunk) {
        int off = 64 + chunk * 64 - (chunk * (chunk - 1)) / 2 + (k - chunk);
        v = fc_w[o * 2144 + off];                              // triu(i=chunk, j=k)
    }
    g_Wh[idx] = __float2half_rn(v);
}

// load this CTA's output-half of A[chunk]: [128 o][64 k] f16
__device__ __forceinline__ void load_A(uint32_t dstStage, int chunk, int tid, int ohalf) {
    const int ks16 = (chunk < 64) ? (chunk >> 4) : 0;
    const int o = tid >> 1, h = tid & 1;                     // 128 rows, 2 thr/row
    const __half* src = g_Wh + (size_t)chunk * WSTRIDE + (size_t)(ohalf * 128 + o) * 64 + h * 8;
#pragma unroll
    for (int kt = 0; kt < 4; kt++) {
        if (kt >= ks16) {
            uint32_t d = dstStage + SWZ((uint32_t)(o * 128 + kt * 32 + h * 16));
            cp16(d, src + kt * 16);
        }
    }
}

// produce B[chunk]: B[p][k] = x_chunk[p]*x_k[p] in f16 (each thread: 2 k-blocks)
__device__ __forceinline__ void produce_B(char* smem, const float* xs, int chunk, int bp, int bks2) {
    const int ks16 = (chunk < 64) ? (chunk >> 4) : 0;
    const float xi = (chunk < 64) ? xs[chunk * PTILE + bp] : 1.0f;
    char* bbase = smem + SM_B + (chunk & 1) * 16384;
#pragma unroll
    for (int b2 = 0; b2 < 2; b2++) {
        const int kb = bks2 * 2 + b2;
        if (kb < ks16) continue;
        __half2 h[8];
#pragma unroll
        for (int j = 0; j < 8; j++) {
            float a0 = xs[(kb * 16 + 2 * j) * PTILE + bp];
            float a1 = xs[(kb * 16 + 2 * j + 1) * PTILE + bp];
            h[j] = __floats2half2_rn(xi * a0, xi * a1);
        }
        const uint32_t ro = (uint32_t)bp * 128 + kb * 32;
        *(uint4*)(bbase + SWZ(ro))      = *(uint4*)&h[0];
        *(uint4*)(bbase + SWZ(ro + 16)) = *(uint4*)&h[4];
    }
}

// ---- main: 512 CTAs x 256 threads; CTA = 128 outputs x 128 pixels; 2 CTAs/SM ----
__global__ void __launch_bounds__(NTHREADS, 2)
quad_main(const float* __restrict__ x, float* __restrict__ out) {
    extern __shared__ __align__(1024) char smem[];
    const uint32_t sb = s2u(smem);
    const int tid = threadIdx.x;
    const int lane = tid & 31;
    const int wid = tid >> 5;
    const int mw = wid & 1;          // output 64-block (2)
    const int nw = wid >> 1;         // pixel  32-block (4)

    const int ohalf = blockIdx.x & 1;               // output half
    const int hw0   = ((blockIdx.x >> 1) & 31) << 7; // pixel tile base (128)
    const int bidx  = blockIdx.x >> 6;               // batch

    float* xs = (float*)(smem + SM_XS);             // [c][p] fp32

    // prefetch A chunk 0 (this CTA's output half)
    load_A(sb + SM_A, 0, tid, ohalf);
    CP_COMMIT();

    // load x tile [64][128]
    {
        const float4* xg = (const float4*)(x + (size_t)bidx * CC * HWN + hw0);
#pragma unroll
        for (int j = 0; j < 8; j++) {
            int idx = tid + j * NTHREADS;       // 0..2047
            int c = idx >> 5, p4 = idx & 31;
            ((float4*)xs)[c * 32 + p4] = xg[(size_t)c * (HWN / 4) + p4];
        }
    }
    CP_WAIT0();          // own A0 copies done before barrier
    __syncthreads();     // publishes x tile AND everyone's A0 copies

    // producer mapping: lane-contiguous pixels -> conflict-free LDS
    const int bp   = tid & 127;     // producer pixel
    const int bks2 = tid >> 7;      // producer k-block pair {0,1} -> blocks {0,1} or {2,3}

    // produce B[0], publish
    produce_B(smem, xs, 0, bp, bks2);
    __syncthreads();

    // lane-derived ldmatrix offsets
    const int arow  = (lane & 7) + ((lane >> 3) & 1) * 8;   // A: row within 16
    const int acol  = ((lane >> 4) & 1) * 16;               // A: byte offset (hi 8 halves)
    const int b4row = (lane & 7) + ((lane >> 4) & 1) * 8;   // B x4: row within 16 (n)
    const int b4col = ((lane >> 3) & 1) * 16;               // B x4: byte offset (k half)

    float acc[4][4][4];
#pragma unroll
    for (int a = 0; a < 4; a++)
#pragma unroll
        for (int b = 0; b < 4; b++)
#pragma unroll
            for (int c = 0; c < 4; c++) acc[a][b][c] = 0.0f;

#pragma unroll 1
    for (int chunk = 0; chunk < NCHUNK; chunk++) {
        const int s = chunk & 1;
        const int ks16 = (chunk < 64) ? (chunk >> 4) : 0;

        // 1) produce NEXT chunk's B into the other buffer (readers done pre-barrier)
        if (chunk + 1 < NCHUNK)
            produce_B(smem, xs, chunk + 1, bp, bks2);

        // 2) prefetch NEXT A into the buffer freed at the previous barrier
        if (chunk + 1 < NCHUNK) {
            load_A(sb + SM_A + (s ^ 1) * 16384, chunk + 1, tid, ohalf);
            CP_COMMIT();
        }

        // 3) mma on A[s], B[s] — published by the previous barrier
        const uint32_t aA = sb + SM_A + s * 16384;
        const uint32_t aB = sb + SM_B + s * 16384;

#pragma unroll
        for (int kt = 0; kt < 4; kt++) {
            if (kt >= ks16) {
                uint32_t af[4][4];
#pragma unroll
                for (int mt = 0; mt < 4; mt++) {
                    uint32_t addr = aA + SWZ((uint32_t)((mw * 64 + mt * 16 + arow) * 128 + kt * 32 + acol));
                    ldsm_x4(addr, af[mt][0], af[mt][1], af[mt][2], af[mt][3]);
                }
                uint32_t bf[4][2];
#pragma unroll
                for (int nt2 = 0; nt2 < 2; nt2++) {
                    uint32_t addr = aB + SWZ((uint32_t)((nw * 32 + nt2 * 16 + b4row) * 128 + kt * 32 + b4col));
                    ldsm_x4(addr, bf[nt2 * 2][0], bf[nt2 * 2][1], bf[nt2 * 2 + 1][0], bf[nt2 * 2 + 1][1]);
                }
#pragma unroll
                for (int mt = 0; mt < 4; mt++)
#pragma unroll
                    for (int nt = 0; nt < 4; nt++)
                        mma16816(acc[mt][nt], af[mt], bf[nt]);
            }
        }

        // 4) own A[chunk+1] copies complete BEFORE the barrier
        CP_WAIT0();

        // 5) single barrier: publishes B[chunk+1] + all A[chunk+1]; frees stage s
        __syncthreads();
    }

    // ---- epilogue: fp32 accumulators -> out[b][o][hw] ----
#pragma unroll
    for (int mt = 0; mt < 4; mt++) {
#pragma unroll
        for (int nt = 0; nt < 4; nt++) {
            const int o = ohalf * 128 + mw * 64 + mt * 16 + (lane >> 2);
            const int p = nw * 32 + nt * 8 + (lane & 3) * 2;
            float* op = out + ((size_t)bidx * OUTC + o) * HWN + hw0 + p;
            float2 v0 = make_float2(acc[mt][nt][0], acc[mt][nt][1]);
            float2 v1 = make_float2(acc[mt][nt][2], acc[mt][nt][3]);
            *(float2*)op = v0;
            *(float2*)(op + 8 * HWN) = v1;
        }
    }
}

extern "C" void kernel_launch(void* const* d_in, const int* in_sizes, int n_in,
                              void* d_out, int out_size) {
    const float* x    = (const float*)d_in[0];
    const float* fc_w = (const float*)d_in[1];
    float* out = (float*)d_out;

    cudaFuncSetAttribute(quad_main, cudaFuncAttributeMaxDynamicSharedMemorySize, SM_TOTAL);

    prep_kernel<<<1040, 1024>>>(fc_w);            // 65*16384 threads exactly
    quad_main<<<512, NTHREADS, SM_TOTAL>>>(x, out);
}

// round 17
// speedup vs baseline: 1.0469x; 1.0234x over previous
#include <cuda_runtime.h>
#include <cuda_fp16.h>
#include <cstdint>

#define CC       64
#define OUTC     256
#define HWN      4096
#define NCHUNK   65
#define PTILE    128
#define NTHREADS 256
#define WSTRIDE  (OUTC*CC)          // 16384 halves per weight chunk

// smem byte offsets (per CTA: 112KB -> 2 CTAs/SM, 224KB of 227KB)
#define SM_XS    0                   // 32 c2-rows x 128 p x float2 = 32KB
#define SM_A     32768               // 3 stages x 16KB ([128 o][64 k] f16, 128B rows)
#define SM_B     81920               // 2 stages x 16KB ([128 p][64 k] f16, 128B rows)
#define SM_TOTAL 114688

#define SWZ(o) ((o) ^ (((o) >> 3) & 0x70))

__device__ __align__(16) __half g_Wh[NCHUNK * WSTRIDE];   // 2.1MB prepared f16 weights

__device__ __forceinline__ uint32_t s2u(const void* p) {
    uint32_t a;
    asm("{ .reg .u64 t; cvta.to.shared.u64 t, %1; cvt.u32.u64 %0, t; }" : "=r"(a) : "l"(p));
    return a;
}
__device__ __forceinline__ void cp16(uint32_t dst, const void* src) {
    asm volatile("cp.async.cg.shared.global [%0], [%1], 16;" :: "r"(dst), "l"(src) : "memory");
}
#define CP_COMMIT() asm volatile("cp.async.commit_group;" ::: "memory")
#define CP_WAIT1()  asm volatile("cp.async.wait_group 1;" ::: "memory")

__device__ __forceinline__ void ldsm_x4(uint32_t a, uint32_t& r0, uint32_t& r1, uint32_t& r2, uint32_t& r3) {
    asm volatile("ldmatrix.sync.aligned.m8n8.x4.shared.b16 {%0,%1,%2,%3}, [%4];"
                 : "=r"(r0), "=r"(r1), "=r"(r2), "=r"(r3) : "r"(a));
}
__device__ __forceinline__ void mma16816(float* d, const uint32_t* a, const uint32_t* b) {
    asm volatile("mma.sync.aligned.m16n8k16.row.col.f32.f16.f16.f32 "
                 "{%0,%1,%2,%3}, {%4,%5,%6,%7}, {%8,%9}, {%0,%1,%2,%3};"
                 : "+f"(d[0]), "+f"(d[1]), "+f"(d[2]), "+f"(d[3])
                 : "r"(a[0]), "r"(a[1]), "r"(a[2]), "r"(a[3]), "r"(b[0]), "r"(b[1]));
}

// ---- weight prep: fc_w fp32 [256 x 2144] -> g_Wh f16 [chunk][o][k], zero below diag ----
__global__ void prep_kernel(const float* __restrict__ fc_w) {
    int idx = blockIdx.x * blockDim.x + threadIdx.x;   // exactly 65*16384
    int chunk = idx >> 14;
    int rem = idx & 16383;
    int o = rem >> 6;
    int k = rem & 63;
    float v = 0.0f;
    if (chunk == 64) {
        v = fc_w[o * 2144 + k];                                // linear part
    } else if (k >= chunk) {
        int off = 64 + chunk * 64 - (chunk * (chunk - 1)) / 2 + (k - chunk);
        v = fc_w[o * 2144 + off];                              // triu(i=chunk, j=k)
    }
    g_Wh[idx] = __float2half_rn(v);
}

// load this CTA's output-half of A[chunk] into the given stage
__device__ __forceinline__ void load_A(uint32_t dstStage, int chunk, int tid, int ohalf) {
    const int ks16 = (chunk < 64) ? (chunk >> 4) : 0;
    const int o = tid >> 1, h = tid & 1;                     // 128 rows, 2 thr/row
    const __half* src = g_Wh + (size_t)chunk * WSTRIDE + (size_t)(ohalf * 128 + o) * 64 + h * 8;
#pragma unroll
    for (int kt = 0; kt < 4; kt++) {
        if (kt >= ks16) {
            uint32_t d = dstStage + SWZ((uint32_t)(o * 128 + kt * 32 + h * 16));
            cp16(d, src + kt * 16);
        }
    }
}

// produce B[chunk]: B[p][k] = x_chunk[p]*x_k[p] in f16
// xs2 layout: float2 per (c2, p): (x[2*c2][p], x[2*c2+1][p])
// thread owns k-blocks {bks2, bks2+2} -> balanced under triangular skip
__device__ __forceinline__ void produce_B(char* smem, const float2* xs2, int chunk, int bp, int bks2) {
    const int ks16 = (chunk < 64) ? (chunk >> 4) : 0;
    float xi;
    if (chunk < 64) {
        float2 f = xs2[(chunk >> 1) * PTILE + bp];
        xi = (chunk & 1) ? f.y : f.x;
    } else {
        xi = 1.0f;
    }
    char* bbase = smem + SM_B + (chunk & 1) * 16384;
#pragma unroll
    for (int b2 = 0; b2 < 2; b2++) {
        const int kb = bks2 + b2 * 2;
        if (kb < ks16) continue;
        __half2 h[8];
#pragma unroll
        for (int j = 0; j < 8; j++) {
            float2 f = xs2[(kb * 8 + j) * PTILE + bp];   // LDS.64, conflict-free
            h[j] = __floats2half2_rn(xi * f.x, xi * f.y);
        }
        const uint32_t ro = (uint32_t)bp * 128 + kb * 32;
        *(uint4*)(bbase + SWZ(ro))      = *(uint4*)&h[0];
        *(uint4*)(bbase + SWZ(ro + 16)) = *(uint4*)&h[4];
    }
}

// ---- main: 512 CTAs x 256 threads; CTA = 128 outputs x 128 pixels; 2 CTAs/SM ----
__global__ void __launch_bounds__(NTHREADS, 2)
quad_main(const float* __restrict__ x, float* __restrict__ out) {
    extern __shared__ __align__(1024) char smem[];
    const uint32_t sb = s2u(smem);
    const int tid = threadIdx.x;
    const int lane = tid & 31;
    const int wid = tid >> 5;
    const int mw = wid & 1;          // output 64-block (2)
    const int nw = wid >> 1;         // pixel  32-block (4)

    const int ohalf = blockIdx.x & 1;                // output half
    const int hw0   = ((blockIdx.x >> 1) & 31) << 7; // pixel tile base (128)
    const int bidx  = blockIdx.x >> 6;               // batch

    float2* xs2 = (float2*)(smem + SM_XS);           // [c2][p]

    // prefetch A chunks 0 and 1 (groups g0, g1)
    load_A(sb + SM_A,         0, tid, ohalf); CP_COMMIT();
    load_A(sb + SM_A + 16384, 1, tid, ohalf); CP_COMMIT();

    // load x tile, interleave channel pairs: xs2[c2][p] = (x[2c2][p], x[2c2+1][p])
    {
        const float4* xg = (const float4*)(x + (size_t)bidx * CC * HWN + hw0);
#pragma unroll
        for (int j = 0; j < 4; j++) {
            int idx = tid + j * NTHREADS;            // 0..1023 tasks: (c2, p4)
            int c2 = idx >> 5, p4 = idx & 31;
            float4 g0 = xg[(size_t)(2 * c2)     * (HWN / 4) + p4];
            float4 g1 = xg[(size_t)(2 * c2 + 1) * (HWN / 4) + p4];
            float4* dst = (float4*)(xs2 + c2 * PTILE + p4 * 4);
            dst[0] = make_float4(g0.x, g1.x, g0.y, g1.y);
            dst[1] = make_float4(g0.z, g1.z, g0.w, g1.w);
        }
    }
    CP_WAIT1();          // g0 (A0) complete; g1 may be in flight
    __syncthreads();     // publishes x tile + A0

    const int bp   = tid & 127;     // producer pixel (lane-contiguous)
    const int bks2 = tid >> 7;      // producer base k-block {0,1} -> owns {bks2, bks2+2}

    produce_B(smem, xs2, 0, bp, bks2);
    __syncthreads();     // publishes B0

    // lane-derived ldmatrix offsets
    const int arow  = (lane & 7) + ((lane >> 3) & 1) * 8;
    const int acol  = ((lane >> 4) & 1) * 16;
    const int b4row = (lane & 7) + ((lane >> 4) & 1) * 8;
    const int b4col = ((lane >> 3) & 1) * 16;

    float acc[4][4][4];
#pragma unroll
    for (int a = 0; a < 4; a++)
#pragma unroll
        for (int b = 0; b < 4; b++)
#pragma unroll
            for (int c = 0; c < 4; c++) acc[a][b][c] = 0.0f;

    int s3 = 0;                      // A stage = chunk % 3
#pragma unroll 1
    for (int chunk = 0; chunk < NCHUNK; chunk++) {
        const int s2 = chunk & 1;
        const int ks16 = (chunk < 64) ? (chunk >> 4) : 0;

        // 1) produce NEXT chunk's B (its readers finished before the last barrier)
        if (chunk + 1 < NCHUNK)
            produce_B(smem, xs2, chunk + 1, bp, bks2);

        // 2) prefetch A[chunk+2] into the stage freed at the last barrier;
        //    ALWAYS commit (possibly empty) to keep group accounting exact
        {
            int nx = chunk + 2;
            if (nx < NCHUNK) {
                int ns = s3 + 2; if (ns >= 3) ns -= 3;
                load_A(sb + SM_A + ns * 16384, nx, tid, ohalf);
            }
            CP_COMMIT();
        }

        // 3) mma on A[s3], B[s2] — published by the previous barrier
        const uint32_t aA = sb + SM_A + s3 * 16384;
        const uint32_t aB = sb + SM_B + s2 * 16384;

#pragma unroll
        for (int kt = 0; kt < 4; kt++) {
            if (kt >= ks16) {
                uint32_t af[4][4];
#pragma unroll
                for (int mt = 0; mt < 4; mt++) {
                    uint32_t addr = aA + SWZ((uint32_t)((mw * 64 + mt * 16 + arow) * 128 + kt * 32 + acol));
                    ldsm_x4(addr, af[mt][0], af[mt][1], af[mt][2], af[mt][3]);
                }
                uint32_t bf[4][2];
#pragma unroll
                for (int nt2 = 0; nt2 < 2; nt2++) {
                    uint32_t addr = aB + SWZ((uint32_t)((nw * 32 + nt2 * 16 + b4row) * 128 + kt * 32 + b4col));
                    ldsm_x4(addr, bf[nt2 * 2][0], bf[nt2 * 2][1], bf[nt2 * 2 + 1][0], bf[nt2 * 2 + 1][1]);
                }
#pragma unroll
                for (int mt = 0; mt < 4; mt++)
#pragma unroll
                    for (int nt = 0; nt < 4; nt++)
                        mma16816(acc[mt][nt], af[mt], bf[nt]);
            }
        }

        // 4) older group (A[chunk+1]) complete before barrier; newest stays in flight
        CP_WAIT1();

        // 5) barrier publishes B[chunk+1] + A[chunk+1]; frees consumed stages
        __syncthreads();

        if (++s3 == 3) s3 = 0;
    }

    // ---- epilogue: fp32 accumulators -> out[b][o][hw] ----
#pragma unroll
    for (int mt = 0; mt < 4; mt++) {
#pragma unroll
        for (int nt = 0; nt < 4; nt++) {
            const int o = ohalf * 128 + mw * 64 + mt * 16 + (lane >> 2);
            const int p = nw * 32 + nt * 8 + (lane & 3) * 2;
            float* op = out + ((size_t)bidx * OUTC + o) * HWN + hw0 + p;
            float2 v0 = make_float2(acc[mt][nt][0], acc[mt][nt][1]);
            float2 v1 = make_float2(acc[mt][nt][2], acc[mt][nt][3]);
            *(float2*)op = v0;
            *(float2*)(op + 8 * HWN) = v1;
        }
    }
}

extern "C" void kernel_launch(void* const* d_in, const int* in_sizes, int n_in,
                              void* d_out, int out_size) {
    const float* x    = (const float*)d_in[0];
    const float* fc_w = (const float*)d_in[1];
    float* out = (float*)d_out;

    cudaFuncSetAttribute(quad_main, cudaFuncAttributeMaxDynamicSharedMemorySize, SM_TOTAL);

    prep_kernel<<<1040, 1024>>>(fc_w);            // 65*16384 threads exactly
    quad_main<<<512, NTHREADS, SM_TOTAL>>>(x, out);
}